// round 3
// baseline (speedup 1.0000x reference)
#include <cuda_runtime.h>
#include <cstdint>
#include <cstddef>

// Correlation cost volume:
//   out[b,i,h,x] = (1/128) * sum_c L[b,c,h,x] * R[b,c,h,x-i],  x>=i, else 0
// b=8, c=128, h=96, w=320, D=48.
//
// R2: f32x2 packed FFMA (PTX-only FFMA2), 960 small CTAs (2/SM) for wave
// balance, shift/mask-only producer addressing (R rows padded to 512B).

namespace {
constexpr int kB = 8, kC = 128, kH = 96, kW = 320, kD = 48;
constexpr int CHW = kH * kW;            // 30720
constexpr int R_PER_BLK = 4;            // (b,h) rows per block
constexpr int TX = 64;                  // x-tile width
constexpr int CCH = 16;                 // channels per chunk
constexpr int NCHUNK = kC / CCH;        // 8
constexpr int LROWB = TX * 4;           // 256 B per (row,c) left line (16 granules)
constexpr int RROWB = 512;              // right line padded to 32 granules (28 used)
constexpr int ROWS_PER_CHUNK = R_PER_BLK * CCH;        // 64
constexpr int LBYTES = ROWS_PER_CHUNK * LROWB;         // 16384
constexpr int RBYTES = ROWS_PER_CHUNK * RROWB;         // 32768
constexpr int BUFB   = LBYTES + RBYTES;                // 49152
constexpr int NT = 192;                 // 6 warps: warp = 8 xg x 4 r, one ig each
constexpr int LSLOTS = ROWS_PER_CHUNK * 16;            // 1024
constexpr int RSLOTS = ROWS_PER_CHUNK * 32;            // 2048 (28/32 issued)
}

// Granule (16B) swizzle: 8 consecutive same-parity granules -> permutation mod 8.
__device__ __forceinline__ uint32_t swz16(uint32_t g) { return g ^ ((g >> 3) & 1u); }

__device__ __forceinline__ void cp_async16(uint32_t dst, const float* src, uint32_t nbytes) {
    asm volatile("cp.async.cg.shared.global [%0], [%1], 16, %2;\n"
                 :: "r"(dst), "l"(src), "r"(nbytes));
}
__device__ __forceinline__ void cp_commit() { asm volatile("cp.async.commit_group;\n" ::: "memory"); }
template <int N>
__device__ __forceinline__ void cp_wait() { asm volatile("cp.async.wait_group %0;\n" :: "n"(N) : "memory"); }

// Packed f32x2 FMA: d = a*b + d (elementwise on fp32 pairs). PTX-only on sm_103a.
__device__ __forceinline__ void ffma2(unsigned long long& d,
                                      unsigned long long a, unsigned long long b) {
    asm("fma.rn.f32x2 %0, %1, %2, %0;" : "+l"(d) : "l"(a), "l"(b));
}
// Odd pair: (hi32(a), lo32(b)).
__device__ __forceinline__ unsigned long long mkO(unsigned long long a,
                                                  unsigned long long b) {
    unsigned long long o;
    asm("{\n\t.reg .b32 al, ah, bl, bh;\n\t"
        "mov.b64 {al, ah}, %1;\n\t"
        "mov.b64 {bl, bh}, %2;\n\t"
        "mov.b64 %0, {ah, bl};\n\t}"
        : "=l"(o) : "l"(a), "l"(b));
    return o;
}
__device__ __forceinline__ void unpack2(float& lo, float& hi, unsigned long long v) {
    asm("mov.b64 {%0, %1}, %2;" : "=f"(lo), "=f"(hi) : "l"(v));
}

extern __shared__ float smem_f[];

__global__ __launch_bounds__(NT, 2)
void costvol_kernel(const float* __restrict__ L, const float* __restrict__ R,
                    float* __restrict__ out) {
    const int tid = threadIdx.x;
    const int X  = blockIdx.x * TX;          // x-tile start
    const int rg = blockIdx.y;               // row group (4 (b,h) rows)

    const uint32_t smemU = (uint32_t)__cvta_generic_to_shared(smem_f);
    char* smem = (char*)smem_f;

    // Compute-thread coordinates (warp = 8 xg x 4 r, fixed ig)
    const int xg = tid & 7;                  // x group (8 x each)
    const int r  = (tid >> 3) & 3;           // row within block
    const int ig = tid >> 5;                 // disparity group 0..5 (8 i each)

    // 96 % 4 == 0 -> all 4 rows of a block share the same batch b.
    const int b  = rg / (kH / R_PER_BLK);    // rg / 24
    const int h0 = (rg % (kH / R_PER_BLK)) * R_PER_BLK;
    const int h  = h0 + r;

    // Global base pointers for this block's row group (c0 added per chunk).
    const float* Lblk = L + ((size_t)(b * kC) * kH + h0) * kW + X;
    const float* Rblk = R + ((size_t)(b * kC) * kH + h0) * kW;   // x=0 of rows

    unsigned long long acc2[8][4];
#pragma unroll
    for (int a = 0; a < 8; a++)
#pragma unroll
        for (int j = 0; j < 4; j++) acc2[a][j] = 0ull;

    // -------- producer: stage one c-chunk (16 channels) --------
    auto produce = [&](int chunk, int buf) {
        const int c0f = chunk * CCH * CHW;           // float offset of chunk
        const uint32_t base = smemU + (uint32_t)buf * BUFB;
        // Left: 1024 granules; row = r2*16+cc, g = idx&15
#pragma unroll 1
        for (int idx = tid; idx < LSLOTS; idx += NT) {
            const int g   = idx & 15;
            const int row = idx >> 4;
            const int cc  = row & 15;
            const int r2  = row >> 4;
            const float* src = Lblk + c0f + cc * CHW + r2 * kW + g * 4;
            cp_async16(base + (uint32_t)row * LROWB + swz16(g) * 16, src, 16u);
        }
        // Right: rows padded to 32 granules, 28 real; window starts at x = X-48
#pragma unroll 1
        for (int idx = tid; idx < RSLOTS; idx += NT) {
            const int g   = idx & 31;
            const int row = idx >> 5;
            if (g < 28) {
                const int cc = row & 15;
                const int r2 = row >> 4;
                const int xs = X - kD + g * 4;       // absolute x (may be <0 only at X=0)
                const float* rowp = Rblk + c0f + cc * CHW + r2 * kW;
                cp_async16(base + LBYTES + (uint32_t)row * RROWB + swz16(g) * 16,
                           rowp + (xs > 0 ? xs : 0), xs >= 0 ? 16u : 0u);
            }
        }
        cp_commit();
    };

    // -------- consumer: per-thread swizzled smem offsets --------
    const uint32_t offL0 = swz16(2u * xg)      * 16u;
    const uint32_t offL1 = swz16(2u * xg + 1u) * 16u;
    const int gR0 = 10 + 2 * (xg - ig);        // window start granule in [0,24]
    const uint32_t offR0 = swz16(gR0)     * 16u;
    const uint32_t offR1 = swz16(gR0 + 1) * 16u;
    const uint32_t offR2 = swz16(gR0 + 2) * 16u;
    const uint32_t offR3 = swz16(gR0 + 3) * 16u;

    auto compute = [&](int buf) {
        const char* sL = smem + (size_t)buf * BUFB + (size_t)r * (16 * LROWB);
        const char* sR = smem + (size_t)buf * BUFB + LBYTES + (size_t)r * (16 * RROWB);
#pragma unroll 2
        for (int cc = 0; cc < CCH; cc++) {
            // L: 8 floats = 4 natural even pairs
            const ulonglong2 la = *(const ulonglong2*)(sL + cc * LROWB + offL0);
            const ulonglong2 lb = *(const ulonglong2*)(sL + cc * LROWB + offL1);
            const unsigned long long Lp[4] = {la.x, la.y, lb.x, lb.y};
            // R window: 16 floats = 8 natural even pairs E, 7 packed odd pairs O
            const ulonglong2 q0 = *(const ulonglong2*)(sR + cc * RROWB + offR0);
            const ulonglong2 q1 = *(const ulonglong2*)(sR + cc * RROWB + offR1);
            const ulonglong2 q2 = *(const ulonglong2*)(sR + cc * RROWB + offR2);
            const ulonglong2 q3 = *(const ulonglong2*)(sR + cc * RROWB + offR3);
            const unsigned long long E[8] = {q0.x, q0.y, q1.x, q1.y,
                                             q2.x, q2.y, q3.x, q3.y};
            unsigned long long O[7];
#pragma unroll
            for (int t = 0; t < 7; t++) O[t] = mkO(E[t], E[t + 1]);
            // Rw[w] = right float at window index w; pair for (di, dx=2j..2j+1)
            // needs (Rw[8+2j-di], Rw[9+2j-di]):
            //   di=2m   -> E[4+j-m];  di=2m+1 -> O[3+j-m]
#pragma unroll
            for (int m = 0; m < 4; m++)
#pragma unroll
                for (int j = 0; j < 4; j++) {
                    ffma2(acc2[2 * m][j],     Lp[j], E[4 + j - m]);
                    ffma2(acc2[2 * m + 1][j], Lp[j], O[3 + j - m]);
                }
        }
    };

    // -------- double-buffered pipeline over c-chunks --------
    produce(0, 0);
    int buf = 0;
#pragma unroll 1
    for (int k = 0; k < NCHUNK; k++) {
        if (k + 1 < NCHUNK) {
            produce(k + 1, buf ^ 1);
            cp_wait<1>();
        } else {
            cp_wait<0>();
        }
        __syncthreads();
        compute(buf);
        __syncthreads();   // protect buf before refill next iteration
        buf ^= 1;
    }

    // -------- epilogue: mean over C, vectorized stores --------
    const float scale = 1.0f / (float)kC;
    float* obase = out + ((size_t)(b * kD + ig * 8) * kH + h) * kW + X + xg * 8;
#pragma unroll
    for (int di = 0; di < 8; di++) {
        float4 v0, v1;
        float p0, p1;
        unpack2(p0, p1, acc2[di][0]); v0.x = p0 * scale; v0.y = p1 * scale;
        unpack2(p0, p1, acc2[di][1]); v0.z = p0 * scale; v0.w = p1 * scale;
        unpack2(p0, p1, acc2[di][2]); v1.x = p0 * scale; v1.y = p1 * scale;
        unpack2(p0, p1, acc2[di][3]); v1.z = p0 * scale; v1.w = p1 * scale;
        float* op = obase + (size_t)di * CHW;
        *(float4*)(op)     = v0;
        *(float4*)(op + 4) = v1;
    }
}

extern "C" void kernel_launch(void* const* d_in, const int* in_sizes, int n_in,
                              void* d_out, int out_size) {
    const float* L = (const float*)d_in[0];
    const float* R = (const float*)d_in[1];
    float* out = (float*)d_out;

    cudaFuncSetAttribute(costvol_kernel,
                         cudaFuncAttributeMaxDynamicSharedMemorySize, 2 * BUFB);

    dim3 grid(kW / TX, (kB * kH) / R_PER_BLK);   // (5, 192) = 960 blocks
    costvol_kernel<<<grid, NT, 2 * BUFB>>>(L, R, out);
}

// round 5
// speedup vs baseline: 1.3905x; 1.3905x over previous
#include <cuda_runtime.h>
#include <cuda_bf16.h>
#include <cstdint>

// Correlation cost volume via warp-level bf16 tensor MMA (3-way bf16 split).
//   out[b,i,h,x] = (1/128) * sum_c L[b,c,h,x] * R[b,c,h,x-i],  x>=i, else 0
// b=8, c=128, h=96, w=320, D=48.
//
// Per (b,h) and 128-wide x-tile: D[m,n] = sum_k A[m,k]*B[n,k] with
// A[m,k]=L[c0+k, X+m], B[n,k]=R[c0+k, X-48+n]; out(i, X+m) = D[m, m+48-i]/128.
// fp32 = hi(bf16)+lo(bf16); D += Ah*Bh + Ah*Bl + Al*Bh (lo*lo negligible).
// Baseline PTX only (mma.sync + ldmatrix) -- tcgen05 rejected by this
// toolchain (.target sm_103 without the 'a' feature set).

namespace {
constexpr int kB = 8, kC = 128, kH = 96, kW = 320, kD = 48;
constexpr int CHW = kH * kW;            // 30720
constexpr int TM = 128;                 // x per CTA tile (MMA M)
constexpr int TN = 176;                 // x' rows staged (X-48 .. X+127)
constexpr int NT = 256;                 // 8 warps, one 16-row m-tile each

constexpr int PITCH  = 128;             // bytes per smem row (64 bf16)
constexpr int A_HALF = TM * PITCH;      // 16384
constexpr int B_HALF = TN * PITCH;      // 22528
constexpr int OFF_A  = 0;               // Ah, Al
constexpr int OFF_B  = 2 * A_HALF;      // Bh, Bl
constexpr int STAGE_BYTES = 2 * A_HALF + 2 * B_HALF;   // 77824
constexpr int BNC_PITCH = 81;           // floats (odd -> CF diagonal reads)
constexpr int SMEM_TOTAL = STAGE_BYTES; // bounce (41472B) overlays staging
}

__device__ __forceinline__ uint32_t smem_u32(const void* p) {
    uint32_t a;
    asm("{ .reg .u64 t; cvta.to.shared.u64 t, %1; cvt.u32.u64 %0, t; }" : "=r"(a) : "l"(p));
    return a;
}

__device__ __forceinline__ void ldsm_x4(uint32_t* r, uint32_t addr) {
    asm volatile("ldmatrix.sync.aligned.m8n8.x4.shared.b16 {%0,%1,%2,%3}, [%4];"
                 : "=r"(r[0]), "=r"(r[1]), "=r"(r[2]), "=r"(r[3]) : "r"(addr));
}

__device__ __forceinline__ void mma_bf16(float* d, const uint32_t* a, const uint32_t* b) {
    asm volatile(
        "mma.sync.aligned.m16n8k16.row.col.f32.bf16.bf16.f32 "
        "{%0,%1,%2,%3}, {%4,%5,%6,%7}, {%8,%9}, {%0,%1,%2,%3};"
        : "+f"(d[0]), "+f"(d[1]), "+f"(d[2]), "+f"(d[3])
        : "r"(a[0]), "r"(a[1]), "r"(a[2]), "r"(a[3]), "r"(b[0]), "r"(b[1]));
}

// fp32x4 -> hi bf16x4 (packed) + residuals
__device__ __forceinline__ uint2 split_hi(float f0, float f1, float f2, float f3,
                                          float& r0, float& r1, float& r2, float& r3) {
    __nv_bfloat162 a = __floats2bfloat162_rn(f0, f1);
    __nv_bfloat162 b = __floats2bfloat162_rn(f2, f3);
    r0 = f0 - __bfloat162float(a.x);
    r1 = f1 - __bfloat162float(a.y);
    r2 = f2 - __bfloat162float(b.x);
    r3 = f3 - __bfloat162float(b.y);
    uint2 v;
    v.x = *reinterpret_cast<uint32_t*>(&a);
    v.y = *reinterpret_cast<uint32_t*>(&b);
    return v;
}
__device__ __forceinline__ uint2 pack_lo(float r0, float r1, float r2, float r3) {
    __nv_bfloat162 a = __floats2bfloat162_rn(r0, r1);
    __nv_bfloat162 b = __floats2bfloat162_rn(r2, r3);
    uint2 v;
    v.x = *reinterpret_cast<uint32_t*>(&a);
    v.y = *reinterpret_cast<uint32_t*>(&b);
    return v;
}

extern __shared__ char smem[];

__global__ __launch_bounds__(NT, 2)
void costvol_mma(const float* __restrict__ L, const float* __restrict__ R,
                 float* __restrict__ out) {
    const uint32_t sb = smem_u32(smem);
    const int tid = threadIdx.x;
    const int wid = tid >> 5;
    const int lid = tid & 31;

    const int tile = blockIdx.x;            // 0..2
    const int bh   = blockIdx.y;            // 0..767
    const int b = bh / kH;
    const int h = bh - b * kH;
    const int X = tile * TM;

    float acc[8][4];                        // 8 n8-subtiles x (m16n8) frag
#pragma unroll
    for (int j = 0; j < 8; j++)
#pragma unroll
        for (int q = 0; q < 4; q++) acc[j][q] = 0.0f;

    // ---- stage one 64-channel chunk into swizzled smem (hi/lo bf16) ----
    auto stage = [&](int u) {
        const int c0 = u * 64;
        // A: 128 x-rows * 16 channel-quads = 2048 slots (8 iters)
#pragma unroll
        for (int s0 = 0; s0 < 2048; s0 += NT) {
            const int s  = s0 + tid;
            const int x  = s & 127;
            const int cq = s >> 7;
            const bool ok = (X + x) < kW;
            const float* p = L + ((long)(b * kC + c0 + 4 * cq) * kH + h) * kW + X + x;
            float f0 = ok ? p[0]       : 0.f;
            float f1 = ok ? p[CHW]     : 0.f;
            float f2 = ok ? p[2 * CHW] : 0.f;
            float f3 = ok ? p[3 * CHW] : 0.f;
            float r0, r1, r2, r3;
            const uint2 hv = split_hi(f0, f1, f2, f3, r0, r1, r2, r3);
            const uint2 lv = pack_lo(r0, r1, r2, r3);
            const uint32_t off = (uint32_t)x * PITCH
                               + (uint32_t)(((cq >> 1) ^ (x & 7)) << 4)
                               + (uint32_t)((cq & 1) << 3);
            *reinterpret_cast<uint2*>(smem + OFF_A + off)          = hv;
            *reinterpret_cast<uint2*>(smem + OFF_A + A_HALF + off) = lv;
        }
        // B: 176 x'-rows * 16 quads = 2816 slots (11 iters)
#pragma unroll
        for (int s0 = 0; s0 < 2816; s0 += NT) {
            const int s   = s0 + tid;
            const int cq  = s / TN;
            const int row = s - cq * TN;
            const int xp  = X - kD + row;
            const bool ok = (xp >= 0) && (xp < kW);
            const float* p = R + ((long)(b * kC + c0 + 4 * cq) * kH + h) * kW + xp;
            float f0 = ok ? p[0]       : 0.f;
            float f1 = ok ? p[CHW]     : 0.f;
            float f2 = ok ? p[2 * CHW] : 0.f;
            float f3 = ok ? p[3 * CHW] : 0.f;
            float r0, r1, r2, r3;
            const uint2 hv = split_hi(f0, f1, f2, f3, r0, r1, r2, r3);
            const uint2 lv = pack_lo(r0, r1, r2, r3);
            const uint32_t off = (uint32_t)row * PITCH
                               + (uint32_t)(((cq >> 1) ^ (row & 7)) << 4)
                               + (uint32_t)((cq & 1) << 3);
            *reinterpret_cast<uint2*>(smem + OFF_B + off)          = hv;
            *reinterpret_cast<uint2*>(smem + OFF_B + B_HALF + off) = lv;
        }
    };

    // ---- per-thread ldmatrix lane addressing ----
    const uint32_t sw    = lid & 7;                 // row&7 for both A and B rows
    const uint32_t rA    = 16u * wid + (lid & 15);  // A row for this lane
    const uint32_t aLine = (uint32_t)(lid >> 4);    // k 16B-line half
    const uint32_t aRowBase = sb + OFF_A + rA * PITCH;
    const uint32_t rBoff = (uint32_t)(((lid >> 4) << 3) + (lid & 7));   // 0..15
    const uint32_t bHalf = (uint32_t)((lid >> 3) & 1);
    const uint32_t bRowBase = sb + OFF_B + (16u * wid + rBoff) * PITCH;

    auto domma = [&]() {
#pragma unroll
        for (int ks = 0; ks < 4; ks++) {
            uint32_t ah[4], al[4];
            const uint32_t aAddr = aRowBase + ((((2u * ks + aLine) ^ sw)) << 4);
            ldsm_x4(ah, aAddr);
            ldsm_x4(al, aAddr + A_HALF);
#pragma unroll
            for (int jp = 0; jp < 4; jp++) {
                uint32_t bh4[4], bl4[4];
                const uint32_t bAddr = bRowBase + (uint32_t)(16 * jp) * PITCH
                                     + (((2u * ks + bHalf) ^ sw) << 4);
                ldsm_x4(bh4, bAddr);
                ldsm_x4(bl4, bAddr + B_HALF);
                mma_bf16(acc[2 * jp],     ah, bh4);
                mma_bf16(acc[2 * jp],     ah, bl4);
                mma_bf16(acc[2 * jp],     al, bh4);
                mma_bf16(acc[2 * jp + 1], ah, bh4 + 2);
                mma_bf16(acc[2 * jp + 1], ah, bl4 + 2);
                mma_bf16(acc[2 * jp + 1], al, bh4 + 2);
            }
        }
    };

    stage(0);
    __syncthreads();
    domma();
    __syncthreads();        // all warps done reading before restage
    stage(1);
    __syncthreads();
    domma();
    __syncthreads();        // staging dead; bounce buffer overlays it

    // ---- accumulators -> smem bounce (scaled), diagonal-friendly layout ----
    {
        float* bnc = reinterpret_cast<float*>(smem);
        const float sc = 1.0f / (float)kC;
        const int q = lid >> 2;             // 0..7
        const int e = lid & 3;              // 0..3
        const int m0 = 16 * wid + q;
#pragma unroll
        for (int j = 0; j < 8; j++) {
            const int col = 8 * j + 2 * e;
            bnc[m0 * BNC_PITCH + col]           = acc[j][0] * sc;
            bnc[m0 * BNC_PITCH + col + 1]       = acc[j][1] * sc;
            bnc[(m0 + 8) * BNC_PITCH + col]     = acc[j][2] * sc;
            bnc[(m0 + 8) * BNC_PITCH + col + 1] = acc[j][3] * sc;
        }
    }
    __syncthreads();

    // ---- out[b,i,h,X+xl] = bounce[xl][(xl&15) + 48 - i], coalesced in x ----
    const int xl = tid & 127;
    if (X + xl < kW) {
        const float* bnr = reinterpret_cast<const float*>(smem)
                         + xl * BNC_PITCH + (xl & 15) + 48;
        float* ob = out + (long)(b * kD) * CHW + h * kW + X + xl;
#pragma unroll
        for (int it = 0; it < 24; it++) {
            const int i = 2 * it + (tid >> 7);
            ob[(long)i * CHW] = bnr[-i];
        }
    }
}

extern "C" void kernel_launch(void* const* d_in, const int* in_sizes, int n_in,
                              void* d_out, int out_size) {
    const float* L = (const float*)d_in[0];
    const float* R = (const float*)d_in[1];
    float* out = (float*)d_out;

    cudaFuncSetAttribute(costvol_mma,
                         cudaFuncAttributeMaxDynamicSharedMemorySize, SMEM_TOTAL);

    dim3 grid((kW + TM - 1) / TM, kB * kH);   // (3, 768) = 2304 CTAs
    costvol_mma<<<grid, NT, SMEM_TOTAL>>>(L, R, out);
}